// round 14
// baseline (speedup 1.0000x reference)
#include <cuda_runtime.h>
#include <cstdint>

// PointPillars scatter, inverted as index-map + gather (PDL-chained).
// B=4, C=64, H=512, W=512, P read from in_sizes.
//
// Init-free map: g_map holds (pid+1), 0 = empty. Zero-initialized at module
// load; gather self-cleans consumed cells so every graph replay starts from
// a clean map (gather -> next-replay scatter is stream-ordered).
//
// Evidence matrix (rounds 5-13): gather pinned at ~58-60us, DRAM ~65%,
// invariant to occupancy (30-89%), cache policy, store width, thread
// mapping, and load coalescing (r13 cut L1 pressure 61->45% and got
// SLOWER) -> the binding resource is DRAM read/write turnaround on the
// ~364 MB mixed stream. Block barriers after random reads are catastrophic
// (r7); warp-shfl load coupling loses (r13); grid-barrier fusion loses to
// PDL (r11); ILP-4 scatter loses (r12).
// This round: r9 structure + chunked load/store interleave in the gather
// (4 chunks of 4 loads + 16 stores) so the write stream starts earlier and
// register count drops; address math hoisted above the PDL wait.
#define B_ 4
#define C_ 64
#define H_ 512
#define W_ 512
#define HW_ (H_ * W_)        // 262144 = 2^18
#define BHW_ (B_ * HW_)      // 1048576

__device__ int g_map[BHW_];  // zero-initialized at load; 0 = empty

// ---------------------------------------------------------------------------
// Kernel 1: scatter (pid+1) per pillar. atomicMax => highest pillar index
// wins == the reference's sequential last-write-wins.
__global__ void __launch_bounds__(512) k_scatter_idx(const int* __restrict__ coords, int P) {
    int p = blockIdx.x * blockDim.x + threadIdx.x;
    if (p < P) {
        int4 c = __ldcs(reinterpret_cast<const int4*>(coords) + p);  // [b,z,y,x]
        int b = c.x, y = c.z, x = c.w;
        if ((unsigned)y < H_ && (unsigned)x < W_) {
            atomicMax(&g_map[(b * H_ + y) * W_ + x], p + 1);
        }
    }
    cudaTriggerProgrammaticLaunchCompletion();
}

// ---------------------------------------------------------------------------
// Kernel 2: gather + self-clean. One thread per BEV cell owns all 64
// channels. Chunked: four rounds of (4x float4 contiguous feature loads ->
// 16 strided channel stores), so writes begin after the first 64B of the
// row instead of after all 256B. Loads streaming (__ldcs), stores
// streaming (__stcs), no smem, no block barriers.
__global__ void __launch_bounds__(256) k_gather(const float* __restrict__ feat,
                                                float* __restrict__ out) {
    int s = blockIdx.x * blockDim.x + threadIdx.x;   // 0 .. BHW_-1
    int b  = s >> 18;            // / HW_
    int sp = s & (HW_ - 1);      // within-batch spatial index

    // Address math overlaps the PDL wait below.
    float* op = out + (size_t)b * (C_ * HW_) + sp;
    int* mp = &g_map[s];

    cudaGridDependencySynchronize();   // scatter grid fully complete

    int v = *mp;

    if (v > 0) {
        *mp = 0;                 // self-clean for next graph replay
        const float4* fp = reinterpret_cast<const float4*>(feat + (size_t)(v - 1) * C_);
#pragma unroll
        for (int ch = 0; ch < 4; ch++) {             // 16-channel chunk
            float4 r0 = __ldcs(fp + 4 * ch + 0);
            float4 r1 = __ldcs(fp + 4 * ch + 1);
            float4 r2 = __ldcs(fp + 4 * ch + 2);
            float4 r3 = __ldcs(fp + 4 * ch + 3);
            float* o = op + (size_t)(16 * ch) * HW_;
            __stcs(o + (size_t) 0 * HW_, r0.x); __stcs(o + (size_t) 1 * HW_, r0.y);
            __stcs(o + (size_t) 2 * HW_, r0.z); __stcs(o + (size_t) 3 * HW_, r0.w);
            __stcs(o + (size_t) 4 * HW_, r1.x); __stcs(o + (size_t) 5 * HW_, r1.y);
            __stcs(o + (size_t) 6 * HW_, r1.z); __stcs(o + (size_t) 7 * HW_, r1.w);
            __stcs(o + (size_t) 8 * HW_, r2.x); __stcs(o + (size_t) 9 * HW_, r2.y);
            __stcs(o + (size_t)10 * HW_, r2.z); __stcs(o + (size_t)11 * HW_, r2.w);
            __stcs(o + (size_t)12 * HW_, r3.x); __stcs(o + (size_t)13 * HW_, r3.y);
            __stcs(o + (size_t)14 * HW_, r3.z); __stcs(o + (size_t)15 * HW_, r3.w);
        }
    } else {
#pragma unroll
        for (int c = 0; c < C_; c++) {
            __stcs(op + (size_t)c * HW_, 0.f);
        }
    }
}

// ---------------------------------------------------------------------------
extern "C" void kernel_launch(void* const* d_in, const int* in_sizes, int n_in,
                              void* d_out, int out_size) {
    const float* feat   = (const float*)d_in[0];   // [P, C] float32
    const int*   coords = (const int*)d_in[1];     // [P, 4] int32
    int P = in_sizes[1] / 4;

    k_scatter_idx<<<(P + 511) / 512, 512>>>(coords, P);

    // Gather with programmatic dependent launch on the scatter.
    cudaLaunchConfig_t cfg = {};
    cfg.gridDim  = dim3(BHW_ / 256);
    cfg.blockDim = dim3(256);
    cfg.stream   = 0;  // capture stream
    cudaLaunchAttribute attr[1];
    attr[0].id = cudaLaunchAttributeProgrammaticStreamSerialization;
    attr[0].val.programmaticStreamSerializationAllowed = 1;
    cfg.attrs    = attr;
    cfg.numAttrs = 1;
    cudaLaunchKernelEx(&cfg, k_gather, feat, (float*)d_out);
}

// round 15
// speedup vs baseline: 2.0886x; 2.0886x over previous
#include <cuda_runtime.h>
#include <cstdint>

// PointPillars scatter, inverted as index-map + gather (PDL-chained).
// B=4, C=64, H=512, W=512, P read from in_sizes.
//
// Init-free map: g_map holds (pid+1), 0 = empty. Zero-initialized at module
// load; gather self-cleans consumed cells so every graph replay starts from
// a clean map (gather -> next-replay scatter is stream-ordered).
//
// FINAL FORM (champion = round 9, 63.33us). Evidence matrix, rounds 5-14:
//  - gather floor ~58-60us at DRAM ~65%: invariant to occupancy (30-89%),
//    cache policy, store width, and thread mapping.
//  - FRONT-BATCHED 16x LDG.128 is load-bearing: chunked load/store
//    interleave (r14) collapsed MLP 16->4 and doubled runtime.
//  - block barriers after the random reads are catastrophic (r7);
//    warp-shfl load cooperation loses (r13); software grid-barrier fusion
//    loses to PDL (r11); ILP-4 scatter loses (r12); smem staging loses
//    (r7, r13). Do not reintroduce any of these.
#define B_ 4
#define C_ 64
#define H_ 512
#define W_ 512
#define HW_ (H_ * W_)        // 262144 = 2^18
#define BHW_ (B_ * HW_)      // 1048576

__device__ int g_map[BHW_];  // zero-initialized at load; 0 = empty

// ---------------------------------------------------------------------------
// Kernel 1: scatter (pid+1) per pillar. atomicMax => highest pillar index
// wins == the reference's sequential last-write-wins.
__global__ void __launch_bounds__(512) k_scatter_idx(const int* __restrict__ coords, int P) {
    int p = blockIdx.x * blockDim.x + threadIdx.x;
    if (p < P) {
        int4 c = __ldcs(reinterpret_cast<const int4*>(coords) + p);  // [b,z,y,x]
        int b = c.x, y = c.z, x = c.w;
        if ((unsigned)y < H_ && (unsigned)x < W_) {
            atomicMax(&g_map[(b * H_ + y) * W_ + x], p + 1);
        }
    }
    cudaTriggerProgrammaticLaunchCompletion();
}

// ---------------------------------------------------------------------------
// Kernel 2: gather + self-clean. One thread per BEV cell owns all 64
// channels: 16x float4 contiguous feature-row reads FRONT-BATCHED (MLP=16,
// streaming), then 64 strided channel stores coalesced across the warp in
// w (streaming). Address math overlaps the PDL wait. No smem, no barriers.
__global__ void __launch_bounds__(256) k_gather(const float* __restrict__ feat,
                                                float* __restrict__ out) {
    int s = blockIdx.x * blockDim.x + threadIdx.x;   // 0 .. BHW_-1
    int b  = s >> 18;            // / HW_
    int sp = s & (HW_ - 1);      // within-batch spatial index

    // Overlaps the PDL dependency wait below.
    float* op = out + (size_t)b * (C_ * HW_) + sp;
    int*   mp = &g_map[s];

    cudaGridDependencySynchronize();   // scatter grid fully complete

    int v = *mp;

    float4 r[16];
    if (v > 0) {
        *mp = 0;                 // self-clean for next graph replay
        const float4* fp = reinterpret_cast<const float4*>(feat + (size_t)(v - 1) * C_);
#pragma unroll
        for (int i = 0; i < 16; i++) r[i] = __ldcs(fp + i);
    } else {
#pragma unroll
        for (int i = 0; i < 16; i++) r[i] = make_float4(0.f, 0.f, 0.f, 0.f);
    }

#pragma unroll
    for (int i = 0; i < 16; i++) {
        __stcs(op + (size_t)(4 * i + 0) * HW_, r[i].x);
        __stcs(op + (size_t)(4 * i + 1) * HW_, r[i].y);
        __stcs(op + (size_t)(4 * i + 2) * HW_, r[i].z);
        __stcs(op + (size_t)(4 * i + 3) * HW_, r[i].w);
    }
}

// ---------------------------------------------------------------------------
extern "C" void kernel_launch(void* const* d_in, const int* in_sizes, int n_in,
                              void* d_out, int out_size) {
    const float* feat   = (const float*)d_in[0];   // [P, C] float32
    const int*   coords = (const int*)d_in[1];     // [P, 4] int32
    int P = in_sizes[1] / 4;

    k_scatter_idx<<<(P + 511) / 512, 512>>>(coords, P);

    // Gather with programmatic dependent launch on the scatter.
    cudaLaunchConfig_t cfg = {};
    cfg.gridDim  = dim3(BHW_ / 256);
    cfg.blockDim = dim3(256);
    cfg.stream   = 0;  // capture stream
    cudaLaunchAttribute attr[1];
    attr[0].id = cudaLaunchAttributeProgrammaticStreamSerialization;
    attr[0].val.programmaticStreamSerializationAllowed = 1;
    cfg.attrs    = attr;
    cfg.numAttrs = 1;
    cudaLaunchKernelEx(&cfg, k_gather, feat, (float*)d_out);
}